// round 10
// baseline (speedup 1.0000x reference)
#include <cuda_runtime.h>
#include <cuda_bf16.h>
#include <cuda_fp16.h>
#include <cstdint>

#define NTOK 65536
#define DDIM 256
#define KCB  1024
#define DECAYF 0.99f
#define ONE_M_DECAY 0.01f
#define EPSF 1e-5f
#define MARGIN 5.0f
#define TAU 0.01f
#define CAP 64

// -------- output layout (floats) --------
#define OFF_LOSS    16777216
#define OFF_ENT     16777217
#define OFF_ENC     16777218
#define OFF_CLUSTER 83886082
#define OFF_EMAW    83887106
#define OFF_EMB     84149250

// -------- static scratch --------
__device__ float          g_flat[NTOK * DDIM];
__device__ __nv_bfloat16  g_flat_bf[NTOK * DDIM];
__device__ __nv_bfloat16  g_emb_bf[KCB * DDIM];
__device__ float          g_e2[KCB];
__device__ unsigned       g_cand[NTOK * CAP];   // packed (fp16 score << 16) | col
__device__ int            g_candn[NTOK];
__device__ int            g_idx[NTOK];
__device__ int            g_counts[KCB];
__device__ int            g_start[KCB];
__device__ int            g_pos[KCB];
__device__ int            g_bucket[NTOK];
__device__ float          g_cluster[KCB];
__device__ float          g_loss_tok[NTOK];

__device__ __forceinline__ void cpa16(uint32_t s, const void* g) {
    asm volatile("cp.async.cg.shared.global [%0],[%1],16;\n" :: "r"(s), "l"(g));
}
#define CPCOMMIT() asm volatile("cp.async.commit_group;\n" ::)
#define LDMX4(r0, r1, r2, r3, addr) \
    asm volatile("ldmatrix.sync.aligned.m8n8.x4.shared.b16 {%0,%1,%2,%3},[%4];" \
                 : "=r"(r0), "=r"(r1), "=r"(r2), "=r"(r3) : "r"(addr))

// ================= K1: NCHW -> NHWC transpose + bf16 =================
__global__ void k_transpose(const float* __restrict__ in) {
    __shared__ float tile[32][33];
    int b = blockIdx.z;
    int hw0 = blockIdx.x * 32;
    int c0  = blockIdx.y * 32;
    int tx = threadIdx.x, ty = threadIdx.y;
#pragma unroll
    for (int j = 0; j < 4; j++) {
        int c = c0 + ty + j * 8;
        tile[ty + j * 8][tx] = in[((size_t)(b * 256 + c) << 10) + hw0 + tx];
    }
    __syncthreads();
#pragma unroll
    for (int j = 0; j < 4; j++) {
        int hw = hw0 + ty + j * 8;
        int c  = c0 + tx;
        float v = tile[tx][ty + j * 8];
        size_t o = ((size_t)(b * 1024 + hw) << 8) + c;
        g_flat[o] = v;
        g_flat_bf[o] = __float2bfloat16(v);
    }
}

// ================= K1b: embedding bf16 + ||e||^2 + per-replay zeroing =================
__global__ void k_embprep(const float* __restrict__ emb) {
    int k = blockIdx.x, t = threadIdx.x;
    if (t == 0) { g_counts[k] = 0; g_pos[k] = 0; }
    int idx = k * 256 + t;
    if (idx < NTOK) g_candn[idx] = 0;
    float v = emb[(size_t)k * DDIM + t];
    g_emb_bf[(size_t)k * DDIM + t] = __float2bfloat16(v);
    float s = v * v;
#pragma unroll
    for (int off = 16; off > 0; off >>= 1) s += __shfl_xor_sync(0xffffffffu, s, off);
    __shared__ float ws[8];
    if ((t & 31) == 0) ws[t >> 5] = s;
    __syncthreads();
    if (t == 0) {
        float tot = 0.f;
#pragma unroll
        for (int i = 0; i < 8; i++) tot += ws[i];
        g_e2[k] = tot;
    }
}

// ================= K2: 3-stage pipelined bf16 GEMM + in-place screening =================
#define PST 40
#define STAGE_ELEMS (2 * 128 * PST)
#define SMEM_GEMM (3 * STAGE_ELEMS * 2)   // 61440 B

__global__ __launch_bounds__(256, 2) void k_gemm() {
    extern __shared__ __nv_bfloat16 sm[];
    int tid = threadIdx.x;
    int warp = tid >> 5, lane = tid & 31;
    int m0 = blockIdx.x * 128;
    int n0 = blockIdx.y * 128;
    int wm = warp & 3, wn = warp >> 2;
    int g = lane >> 2, c = lane & 3;
    uint32_t sb = (uint32_t)__cvta_generic_to_shared(sm);

    int lrow = tid >> 1, lseg = (tid & 1) * 2;

    auto loadstage = [&](int kt, int s) {
        uint32_t base = sb + (uint32_t)(s * STAGE_ELEMS) * 2;
#pragma unroll
        for (int j = 0; j < 2; j++) {
            int seg = lseg + j;
            cpa16(base + (uint32_t)(lrow * PST + seg * 8) * 2,
                  &g_flat_bf[(size_t)(m0 + lrow) * DDIM + kt * 32 + seg * 8]);
            cpa16(base + (uint32_t)(128 * PST + lrow * PST + seg * 8) * 2,
                  &g_emb_bf[(size_t)(n0 + lrow) * DDIM + kt * 32 + seg * 8]);
        }
        CPCOMMIT();
    };

    loadstage(0, 0);
    loadstage(1, 1);

    uint32_t offA = (uint32_t)((wm * 32 + (lane & 15)) * PST + 8 * (lane >> 4)) * 2;
    uint32_t offB[4];
#pragma unroll
    for (int pi = 0; pi < 4; pi++) {
        int row = wn * 64 + pi * 16 + (lane & 7) + ((lane & 16) ? 8 : 0);
        int col = (lane & 8) ? 8 : 0;
        offB[pi] = (uint32_t)(row * PST + col) * 2;
    }

    float acc[2][8][4];
#pragma unroll
    for (int a = 0; a < 2; a++)
#pragma unroll
        for (int b = 0; b < 8; b++)
#pragma unroll
            for (int d = 0; d < 4; d++) acc[a][b][d] = 0.f;

    for (int kt = 0; kt < 8; kt++) {
        if (kt < 7) asm volatile("cp.async.wait_group 1;\n" ::);
        else        asm volatile("cp.async.wait_group 0;\n" ::);
        __syncthreads();

        uint32_t sA = sb + (uint32_t)((kt % 3) * STAGE_ELEMS) * 2;
        uint32_t sB = sA + (uint32_t)(128 * PST) * 2;
#pragma unroll
        for (int ks = 0; ks < 2; ks++) {
            uint32_t kb2 = (uint32_t)(ks * 16) * 2;
            unsigned afr[2][4], bfr[8][2];
            LDMX4(afr[0][0], afr[0][1], afr[0][2], afr[0][3], sA + offA + kb2);
            LDMX4(afr[1][0], afr[1][1], afr[1][2], afr[1][3],
                  sA + offA + kb2 + (uint32_t)(16 * PST) * 2);
#pragma unroll
            for (int pi = 0; pi < 4; pi++) {
                unsigned t0, t1, t2, t3;
                LDMX4(t0, t1, t2, t3, sB + offB[pi] + kb2);
                bfr[2 * pi][0] = t0; bfr[2 * pi][1] = t1;
                bfr[2 * pi + 1][0] = t2; bfr[2 * pi + 1][1] = t3;
            }
#pragma unroll
            for (int mi = 0; mi < 2; mi++)
#pragma unroll
                for (int ni = 0; ni < 8; ni++) {
                    asm volatile(
                        "mma.sync.aligned.m16n8k16.row.col.f32.bf16.bf16.f32 "
                        "{%0,%1,%2,%3},{%4,%5,%6,%7},{%8,%9},{%0,%1,%2,%3};"
                        : "+f"(acc[mi][ni][0]), "+f"(acc[mi][ni][1]),
                          "+f"(acc[mi][ni][2]), "+f"(acc[mi][ni][3])
                        : "r"(afr[mi][0]), "r"(afr[mi][1]), "r"(afr[mi][2]), "r"(afr[mi][3]),
                          "r"(bfr[ni][0]), "r"(bfr[ni][1]));
                }
        }
        if (kt + 2 < 8) loadstage(kt + 2, (kt + 2) % 3);
    }

    // epilogue: in-place transform acc -> score, chunk-min screen, admit candidates
    int colb = n0 + wn * 64;
#pragma unroll
    for (int mi = 0; mi < 2; mi++) {
        int rowA = m0 + wm * 32 + mi * 16 + g;   // rows rowA and rowA+8
        float mnA = 3.4e38f, mnB = 3.4e38f;
#pragma unroll
        for (int ni = 0; ni < 8; ni++) {
            int col = colb + ni * 8 + 2 * c;
            float e2a = __ldg(&g_e2[col]);
            float e2b = __ldg(&g_e2[col + 1]);
            acc[mi][ni][0] = fmaf(-2.f, acc[mi][ni][0], e2a);
            acc[mi][ni][1] = fmaf(-2.f, acc[mi][ni][1], e2b);
            acc[mi][ni][2] = fmaf(-2.f, acc[mi][ni][2], e2a);
            acc[mi][ni][3] = fmaf(-2.f, acc[mi][ni][3], e2b);
            mnA = fminf(mnA, fminf(acc[mi][ni][0], acc[mi][ni][1]));
            mnB = fminf(mnB, fminf(acc[mi][ni][2], acc[mi][ni][3]));
        }
        mnA = fminf(mnA, __shfl_xor_sync(0xffffffffu, mnA, 1));
        mnA = fminf(mnA, __shfl_xor_sync(0xffffffffu, mnA, 2));
        mnB = fminf(mnB, __shfl_xor_sync(0xffffffffu, mnB, 1));
        mnB = fminf(mnB, __shfl_xor_sync(0xffffffffu, mnB, 2));
        float thrA = mnA + MARGIN;
        float thrB = mnB + MARGIN;
#pragma unroll
        for (int ni = 0; ni < 8; ni++) {
#pragma unroll
            for (int d = 0; d < 4; d++) {
                float s = acc[mi][ni][d];
                float thr = (d & 2) ? thrB : thrA;
                if (s <= thr) {
                    int col = colb + ni * 8 + 2 * c + (d & 1);
                    int row = rowA + ((d & 2) ? 8 : 0);
                    int p = atomicAdd(&g_candn[row], 1);
                    if (p < CAP) {
                        unsigned h = (unsigned)__half_as_ushort(__float2half_rn(s));
                        g_cand[(size_t)row * CAP + p] = (h << 16) | (unsigned)col;
                    }
                }
            }
        }
    }
}

// ================= K3: candidate filter + exact refine + enc write =================
__global__ __launch_bounds__(512) void k_refine(float* __restrict__ enc,
                                                const float* __restrict__ emb) {
    __shared__ int candk[16][CAP];
    __shared__ int candn_s[16];

    int tid = threadIdx.x;
    int w = tid >> 5, lane = tid & 31;
    int n = blockIdx.x * 16 + w;

    if (lane == 0) candn_s[w] = 0;
    __syncwarp();

    int cnt = g_candn[n];

    float x[8];
    {
        const float4* xr = (const float4*)&g_flat[(size_t)n * DDIM + lane * 8];
        float4 a = xr[0], b = xr[1];
        x[0]=a.x; x[1]=a.y; x[2]=a.z; x[3]=a.w;
        x[4]=b.x; x[5]=b.y; x[6]=b.z; x[7]=b.w;
    }

    float bestd = 3.4e38f, second = 3.4e38f;
    int bestk = KCB;

    if (cnt <= CAP) {
        unsigned v0 = 0, v1 = 0;
        float s0f = 3.4e38f, s1f = 3.4e38f;
        if (lane < cnt) {
            v0 = g_cand[(size_t)n * CAP + lane];
            s0f = __half2float(__ushort_as_half((unsigned short)(v0 >> 16)));
        }
        if (lane + 32 < cnt) {
            v1 = g_cand[(size_t)n * CAP + lane + 32];
            s1f = __half2float(__ushort_as_half((unsigned short)(v1 >> 16)));
        }
        float mn = fminf(s0f, s1f);
#pragma unroll
        for (int off = 16; off > 0; off >>= 1) mn = fminf(mn, __shfl_xor_sync(0xffffffffu, mn, off));
        float thr = mn + MARGIN;
        if (s0f <= thr) {
            int pos = atomicAdd(&candn_s[w], 1);
            candk[w][pos] = (int)(v0 & 0xffffu);
        }
        if (s1f <= thr) {
            int pos = atomicAdd(&candn_s[w], 1);
            candk[w][pos] = (int)(v1 & 0xffffu);
        }
        __syncwarp();
        int nc = candn_s[w];

        for (int ci = 0; ci < nc; ci++) {
            int kc = candk[w][ci];
            const float4* er = (const float4*)&emb[(size_t)kc * DDIM + lane * 8];
            float4 ea = er[0], eb = er[1];
            float d0=x[0]-ea.x, d1=x[1]-ea.y, d2=x[2]-ea.z, d3=x[3]-ea.w;
            float d4=x[4]-eb.x, d5=x[5]-eb.y, d6=x[6]-eb.z, d7=x[7]-eb.w;
            float pr = d0*d0+d1*d1+d2*d2+d3*d3+d4*d4+d5*d5+d6*d6+d7*d7;
#pragma unroll
            for (int off = 16; off > 0; off >>= 1) pr += __shfl_xor_sync(0xffffffffu, pr, off);
            if (pr < bestd) { second = bestd; bestd = pr; bestk = kc; }
            else if (pr < second) second = pr;
        }
        if (second <= bestd + TAU) {
            double bd = 1e300; int bk = KCB;
            for (int ci = 0; ci < nc; ci++) {
                int kc = candk[w][ci];
                const float4* er = (const float4*)&emb[(size_t)kc * DDIM + lane * 8];
                float4 ea = er[0], eb = er[1];
                double dp = 0.0;
#pragma unroll
                for (int qd = 0; qd < 4; qd++) {
                    double da = (double)x[qd]   - (double)(&ea.x)[qd];
                    double db = (double)x[qd+4] - (double)(&eb.x)[qd];
                    dp += da * da + db * db;
                }
#pragma unroll
                for (int off = 16; off > 0; off >>= 1) dp += __shfl_xor_sync(0xffffffffu, dp, off);
                if (dp < bd || (dp == bd && kc < bk)) { bd = dp; bk = kc; }
            }
            bestk = bk; bestd = (float)bd;
        }
    } else {
        // overflow fallback: full exact scan
        for (int kc = 0; kc < KCB; kc++) {
            const float4* er = (const float4*)&emb[(size_t)kc * DDIM + lane * 8];
            float4 ea = er[0], eb = er[1];
            float d0=x[0]-ea.x, d1=x[1]-ea.y, d2=x[2]-ea.z, d3=x[3]-ea.w;
            float d4=x[4]-eb.x, d5=x[5]-eb.y, d6=x[6]-eb.z, d7=x[7]-eb.w;
            float pr = d0*d0+d1*d1+d2*d2+d3*d3+d4*d4+d5*d5+d6*d6+d7*d7;
#pragma unroll
            for (int off = 16; off > 0; off >>= 1) pr += __shfl_xor_sync(0xffffffffu, pr, off);
            if (pr < bestd) { second = bestd; bestd = pr; bestk = kc; }
            else if (pr < second) second = pr;
        }
        if (second <= bestd + TAU) {
            double bd = 1e300; int bk = KCB;
            for (int kc = 0; kc < KCB; kc++) {
                const float4* er = (const float4*)&emb[(size_t)kc * DDIM + lane * 8];
                float4 ea = er[0], eb = er[1];
                float d0=x[0]-ea.x, d1=x[1]-ea.y, d2=x[2]-ea.z, d3=x[3]-ea.w;
                float d4=x[4]-eb.x, d5=x[5]-eb.y, d6=x[6]-eb.z, d7=x[7]-eb.w;
                float pr = d0*d0+d1*d1+d2*d2+d3*d3+d4*d4+d5*d5+d6*d6+d7*d7;
#pragma unroll
                for (int off = 16; off > 0; off >>= 1) pr += __shfl_xor_sync(0xffffffffu, pr, off);
                if (pr <= bestd + TAU) {
                    double dp = 0.0;
#pragma unroll
                    for (int qd = 0; qd < 4; qd++) {
                        double da = (double)x[qd]   - (double)(&ea.x)[qd];
                        double db = (double)x[qd+4] - (double)(&eb.x)[qd];
                        dp += da * da + db * db;
                    }
#pragma unroll
                    for (int off = 16; off > 0; off >>= 1) dp += __shfl_xor_sync(0xffffffffu, dp, off);
                    if (dp < bd || (dp == bd && kc < bk)) { bd = dp; bk = kc; }
                }
            }
            bestk = bk; bestd = (float)bd;
        }
    }

    // one-hot encodings row
    float2* erow = (float2*)&enc[(size_t)n * KCB];
#pragma unroll
    for (int j = 0; j < 16; j++) {
        int idx2 = lane + 32 * j;
        float2 v;
        v.x = (2 * idx2     == bestk) ? 1.0f : 0.0f;
        v.y = (2 * idx2 + 1 == bestk) ? 1.0f : 0.0f;
        erow[idx2] = v;
    }

    if (lane == 0) {
        g_idx[n] = bestk;
        atomicAdd(&g_counts[bestk], 1);
        g_loss_tok[n] = bestd;
    }
}

// ================= K5: quantized output (NCHW), smem-tiled =================
__global__ void k_out(float* __restrict__ out, const float* __restrict__ emb) {
    __shared__ float tile[32][257];
    __shared__ int kk[32];
    int tid = threadIdx.x;
    int b = blockIdx.y;
    int hw0 = blockIdx.x * 32;

    if (tid < 32) kk[tid] = g_idx[b * 1024 + hw0 + tid];
    __syncthreads();
#pragma unroll 4
    for (int tl = 0; tl < 32; tl++) {
        tile[tl][tid] = __ldg(&emb[((size_t)kk[tl] << 8) + tid]);
    }
    __syncthreads();
    int hw = tid & 31;
    int cb = tid >> 5;
#pragma unroll 4
    for (int cc = 0; cc < 32; cc++) {
        int ch = cb * 32 + cc;
        out[((size_t)(b * 256 + ch) << 10) + hw0 + hw] = tile[hw][ch];
    }
}

// ================= K6: finalize (warp scans + loss reduce) =================
__global__ void k_finalize(const float* __restrict__ ema_cs,
                           float* __restrict__ cluster_o,
                           float* __restrict__ loss_o,
                           float* __restrict__ ent_o) {
    __shared__ int    wsum[32];
    __shared__ float  red[32];
    __shared__ double dred[32];
    int t = threadIdx.x, w = t >> 5, l = t & 31;
    int cnt = g_counts[t];

    double ls = 0.0;
#pragma unroll 8
    for (int i = 0; i < NTOK / 1024; i++) ls += (double)g_loss_tok[t + i * 1024];
#pragma unroll
    for (int off = 16; off > 0; off >>= 1) ls += __shfl_xor_sync(0xffffffffu, ls, off);
    if (l == 0) dred[w] = ls;

    int v = cnt;
#pragma unroll
    for (int off = 1; off < 32; off <<= 1) {
        int u = __shfl_up_sync(0xffffffffu, v, off);
        if (l >= off) v += u;
    }
    if (l == 31) wsum[w] = v;
    __syncthreads();
    if (w == 0) {
        int s = wsum[l];
#pragma unroll
        for (int off = 1; off < 32; off <<= 1) {
            int u = __shfl_up_sync(0xffffffffu, s, off);
            if (l >= off) s += u;
        }
        wsum[l] = s;
    }
    __syncthreads();
    int base = (w > 0) ? wsum[w - 1] : 0;
    g_start[t] = base + v - cnt;

    float cl = ema_cs[t] * DECAYF + ONE_M_DECAY * (float)cnt;
    float sv = cl;
#pragma unroll
    for (int off = 16; off > 0; off >>= 1) sv += __shfl_xor_sync(0xffffffffu, sv, off);
    if (l == 0) red[w] = sv;
    __syncthreads();
    if (w == 0) {
        float z = red[l];
#pragma unroll
        for (int off = 16; off > 0; off >>= 1) z += __shfl_xor_sync(0xffffffffu, z, off);
        red[l] = z;
    }
    __syncthreads();
    float nsum = red[0];
    __syncthreads();

    float cln = ((cl + EPSF) / (nsum + 1024.0f * EPSF)) * nsum;
    g_cluster[t] = cln;
    cluster_o[t] = cln;

    float p = (float)cnt * (1.0f / 65536.0f);
    float e = -p * logf(p + 1e-10f);
    float ev = e;
#pragma unroll
    for (int off = 16; off > 0; off >>= 1) ev += __shfl_xor_sync(0xffffffffu, ev, off);
    if (l == 0) red[w] = ev;
    __syncthreads();
    if (w == 0) {
        double lz = dred[l];
#pragma unroll
        for (int off = 16; off > 0; off >>= 1) lz += __shfl_xor_sync(0xffffffffu, lz, off);
        float z = red[l];
#pragma unroll
        for (int off = 16; off > 0; off >>= 1) z += __shfl_xor_sync(0xffffffffu, z, off);
        if (l == 0) {
            ent_o[0] = z;
            loss_o[0] = (float)(0.25 * lz / 16777216.0);
        }
    }
}

// ================= K7: bucket fill =================
__global__ void k_bucket() {
    int n = blockIdx.x * 256 + threadIdx.x;
    int k = g_idx[n];
    int p = atomicAdd(&g_pos[k], 1);
    g_bucket[g_start[k] + p] = n;
}

// ================= K8: dw + new_ema_w + new_embedding (warp-parallel) =================
__global__ void k_emaw(const float* __restrict__ ema_w,
                       float* __restrict__ emaw_o,
                       float* __restrict__ emb_o) {
    __shared__ float sacc[8][DDIM];
    int k = blockIdx.x;
    int tid = threadIdx.x, w = tid >> 5, lane = tid & 31;
    int cnt = g_counts[k], st = g_start[k];

    float acc[8];
#pragma unroll
    for (int j = 0; j < 8; j++) acc[j] = 0.f;

    for (int i = w; i < cnt; i += 8) {
        int n = g_bucket[st + i];
        const float4* r = (const float4*)&g_flat[(size_t)n * DDIM + lane * 8];
        float4 a = r[0], b = r[1];
        acc[0] += a.x; acc[1] += a.y; acc[2] += a.z; acc[3] += a.w;
        acc[4] += b.x; acc[5] += b.y; acc[6] += b.z; acc[7] += b.w;
    }
#pragma unroll
    for (int j = 0; j < 8; j++) sacc[w][lane * 8 + j] = acc[j];
    __syncthreads();

    int d = tid;
    float tot = 0.f;
#pragma unroll
    for (int w2 = 0; w2 < 8; w2++) tot += sacc[w2][d];
    float wv = ema_w[(size_t)k * DDIM + d] * DECAYF + ONE_M_DECAY * tot;
    emaw_o[(size_t)k * DDIM + d] = wv;
    emb_o[(size_t)k * DDIM + d] = wv / g_cluster[k];
}

// ================= launch =================
extern "C" void kernel_launch(void* const* d_in, const int* in_sizes, int n_in,
                              void* d_out, int out_size) {
    const float* inputs    = (const float*)d_in[0];
    const float* embedding = (const float*)d_in[1];
    const float* ema_cs    = (const float*)d_in[2];
    const float* ema_w     = (const float*)d_in[3];

    float* out    = (float*)d_out;
    float* loss_o = out + OFF_LOSS;
    float* ent_o  = out + OFF_ENT;
    float* enc    = out + OFF_ENC;
    float* clus_o = out + OFF_CLUSTER;
    float* emaw_o = out + OFF_EMAW;
    float* emb_o  = out + OFF_EMB;

    cudaFuncSetAttribute(k_gemm, cudaFuncAttributeMaxDynamicSharedMemorySize, SMEM_GEMM);

    k_embprep<<<KCB, 256>>>(embedding);
    k_transpose<<<dim3(32, 8, 64), dim3(32, 8)>>>(inputs);
    k_gemm<<<dim3(NTOK / 128, KCB / 128), 256, SMEM_GEMM>>>();
    k_refine<<<NTOK / 16, 512>>>(enc, embedding);
    k_out<<<dim3(32, 64), 256>>>(out, embedding);
    k_finalize<<<1, 1024>>>(ema_cs, clus_o, loss_o, ent_o);
    k_bucket<<<NTOK / 256, 256>>>();
    k_emaw<<<KCB, 256>>>(ema_w, emaw_o, emb_o);
}

// round 12
// speedup vs baseline: 1.7481x; 1.7481x over previous
#include <cuda_runtime.h>
#include <cuda_bf16.h>
#include <cuda_fp16.h>
#include <cstdint>

#define NTOK 65536
#define DDIM 256
#define KCB  1024
#define DECAYF 0.99f
#define ONE_M_DECAY 0.01f
#define EPSF 1e-5f
#define MARGIN 6.0f
#define TAU 0.01f
#define NCAND 32
#define NREFBLK (NTOK / 8)   // 8192

// -------- output layout (floats) --------
#define OFF_LOSS    16777216
#define OFF_ENT     16777217
#define OFF_ENC     16777218
#define OFF_CLUSTER 83886082
#define OFF_EMAW    83887106
#define OFF_EMB     84149250

// -------- static scratch --------
__device__ float          g_flat[NTOK * DDIM];
__device__ __nv_bfloat16  g_flat_bf[NTOK * DDIM];
__device__ __nv_bfloat16  g_emb_bf[KCB * DDIM];
__device__ float          g_e2[KCB];
__device__ unsigned       g_S[NTOK * (KCB / 2)];   // fp16 scores, packed half2
__device__ int            g_idx[NTOK];
__device__ int            g_counts[KCB];
__device__ int            g_start[KCB];
__device__ int            g_pos[KCB];
__device__ int            g_bucket[NTOK];
__device__ float          g_cluster[KCB];
__device__ double         g_loss_part[NREFBLK];

__device__ __forceinline__ void cpa16(uint32_t s, const void* g) {
    asm volatile("cp.async.cg.shared.global [%0],[%1],16;\n" :: "r"(s), "l"(g));
}
#define CPCOMMIT() asm volatile("cp.async.commit_group;\n" ::)
#define LDMX4(r0, r1, r2, r3, addr) \
    asm volatile("ldmatrix.sync.aligned.m8n8.x4.shared.b16 {%0,%1,%2,%3},[%4];" \
                 : "=r"(r0), "=r"(r1), "=r"(r2), "=r"(r3) : "r"(addr))

// ================= K1: NCHW -> NHWC transpose + bf16 =================
__global__ void k_transpose(const float* __restrict__ in) {
    __shared__ float tile[32][33];
    int b = blockIdx.z;
    int hw0 = blockIdx.x * 32;
    int c0  = blockIdx.y * 32;
    int tx = threadIdx.x, ty = threadIdx.y;
#pragma unroll
    for (int j = 0; j < 4; j++) {
        int c = c0 + ty + j * 8;
        tile[ty + j * 8][tx] = in[((size_t)(b * 256 + c) << 10) + hw0 + tx];
    }
    __syncthreads();
#pragma unroll
    for (int j = 0; j < 4; j++) {
        int hw = hw0 + ty + j * 8;
        int c  = c0 + tx;
        float v = tile[tx][ty + j * 8];
        size_t o = ((size_t)(b * 1024 + hw) << 8) + c;
        g_flat[o] = v;
        g_flat_bf[o] = __float2bfloat16(v);
    }
}

// ================= K1b: embedding bf16 + ||e||^2 + counter zero =================
__global__ void k_embprep(const float* __restrict__ emb) {
    int k = blockIdx.x, t = threadIdx.x;
    if (t == 0) { g_counts[k] = 0; g_pos[k] = 0; }
    float v = emb[(size_t)k * DDIM + t];
    g_emb_bf[(size_t)k * DDIM + t] = __float2bfloat16(v);
    float s = v * v;
#pragma unroll
    for (int off = 16; off > 0; off >>= 1) s += __shfl_xor_sync(0xffffffffu, s, off);
    __shared__ float ws[8];
    if ((t & 31) == 0) ws[t >> 5] = s;
    __syncthreads();
    if (t == 0) {
        float tot = 0.f;
#pragma unroll
        for (int i = 0; i < 8; i++) tot += ws[i];
        g_e2[k] = tot;
    }
}

// ================= K2: 3-stage pipelined bf16 GEMM (ldmatrix) -> fp16 scores =================
#define PST 40
#define STAGE_ELEMS (2 * 128 * PST)
#define SMEM_GEMM (3 * STAGE_ELEMS * 2)   // 61440 B

__global__ __launch_bounds__(256, 2) void k_gemm() {
    extern __shared__ __nv_bfloat16 sm[];
    int tid = threadIdx.x;
    int warp = tid >> 5, lane = tid & 31;
    int m0 = blockIdx.x * 128;
    int n0 = blockIdx.y * 128;
    int wm = warp & 3, wn = warp >> 2;
    int g = lane >> 2, c = lane & 3;
    uint32_t sb = (uint32_t)__cvta_generic_to_shared(sm);

    int lrow = tid >> 1, lseg = (tid & 1) * 2;

    auto loadstage = [&](int kt, int s) {
        uint32_t base = sb + (uint32_t)(s * STAGE_ELEMS) * 2;
#pragma unroll
        for (int j = 0; j < 2; j++) {
            int seg = lseg + j;
            cpa16(base + (uint32_t)(lrow * PST + seg * 8) * 2,
                  &g_flat_bf[(size_t)(m0 + lrow) * DDIM + kt * 32 + seg * 8]);
            cpa16(base + (uint32_t)(128 * PST + lrow * PST + seg * 8) * 2,
                  &g_emb_bf[(size_t)(n0 + lrow) * DDIM + kt * 32 + seg * 8]);
        }
        CPCOMMIT();
    };

    loadstage(0, 0);
    loadstage(1, 1);

    // lane-dependent ldmatrix byte offsets (within a stage)
    uint32_t offA = (uint32_t)((wm * 32 + (lane & 15)) * PST + 8 * (lane >> 4)) * 2;
    uint32_t offB[4];
#pragma unroll
    for (int pi = 0; pi < 4; pi++) {
        int row = wn * 64 + pi * 16 + (lane & 7) + ((lane & 16) ? 8 : 0);
        int col = (lane & 8) ? 8 : 0;
        offB[pi] = (uint32_t)(row * PST + col) * 2;
    }

    float acc[2][8][4];
#pragma unroll
    for (int a = 0; a < 2; a++)
#pragma unroll
        for (int b = 0; b < 8; b++)
#pragma unroll
            for (int d = 0; d < 4; d++) acc[a][b][d] = 0.f;

    for (int kt = 0; kt < 8; kt++) {
        if (kt < 7) asm volatile("cp.async.wait_group 1;\n" ::);
        else        asm volatile("cp.async.wait_group 0;\n" ::);
        __syncthreads();

        uint32_t sA = sb + (uint32_t)((kt % 3) * STAGE_ELEMS) * 2;
        uint32_t sB = sA + (uint32_t)(128 * PST) * 2;
#pragma unroll
        for (int ks = 0; ks < 2; ks++) {
            uint32_t kb2 = (uint32_t)(ks * 16) * 2;
            unsigned afr[2][4], bfr[8][2];
            LDMX4(afr[0][0], afr[0][1], afr[0][2], afr[0][3], sA + offA + kb2);
            LDMX4(afr[1][0], afr[1][1], afr[1][2], afr[1][3],
                  sA + offA + kb2 + (uint32_t)(16 * PST) * 2);
#pragma unroll
            for (int pi = 0; pi < 4; pi++) {
                unsigned t0, t1, t2, t3;
                LDMX4(t0, t1, t2, t3, sB + offB[pi] + kb2);
                bfr[2 * pi][0] = t0; bfr[2 * pi][1] = t1;
                bfr[2 * pi + 1][0] = t2; bfr[2 * pi + 1][1] = t3;
            }
#pragma unroll
            for (int mi = 0; mi < 2; mi++)
#pragma unroll
                for (int ni = 0; ni < 8; ni++) {
                    asm volatile(
                        "mma.sync.aligned.m16n8k16.row.col.f32.bf16.bf16.f32 "
                        "{%0,%1,%2,%3},{%4,%5,%6,%7},{%8,%9},{%0,%1,%2,%3};"
                        : "+f"(acc[mi][ni][0]), "+f"(acc[mi][ni][1]),
                          "+f"(acc[mi][ni][2]), "+f"(acc[mi][ni][3])
                        : "r"(afr[mi][0]), "r"(afr[mi][1]), "r"(afr[mi][2]), "r"(afr[mi][3]),
                          "r"(bfr[ni][0]), "r"(bfr[ni][1]));
                }
        }
        if (kt + 2 < 8) loadstage(kt + 2, (kt + 2) % 3);
    }

    // epilogue: s = e2 - 2*dot -> fp16 half2 packed
#pragma unroll
    for (int mi = 0; mi < 2; mi++) {
        int r0 = m0 + wm * 32 + mi * 16 + g;
#pragma unroll
        for (int ni = 0; ni < 8; ni++) {
            int col = n0 + wn * 64 + ni * 8 + 2 * c;
            float e2a = __ldg(&g_e2[col]);
            float e2b = __ldg(&g_e2[col + 1]);
            __half2 h0 = __floats2half2_rn(fmaf(-2.f, acc[mi][ni][0], e2a),
                                           fmaf(-2.f, acc[mi][ni][1], e2b));
            __half2 h1 = __floats2half2_rn(fmaf(-2.f, acc[mi][ni][2], e2a),
                                           fmaf(-2.f, acc[mi][ni][3], e2b));
            g_S[(size_t)r0 * 512 + (col >> 1)]       = *(unsigned*)&h0;
            g_S[(size_t)(r0 + 8) * 512 + (col >> 1)] = *(unsigned*)&h1;
        }
    }
}

// ================= K3: screen fp16 scores + exact refine + enc write =================
__global__ __launch_bounds__(256) void k_refine(float* __restrict__ enc,
                                                const float* __restrict__ emb) {
    __shared__ int candk[8][NCAND];
    __shared__ int candn[8];
    __shared__ double sloss[8];

    int tid = threadIdx.x;
    int w = tid >> 5, lane = tid & 31;
    int n = blockIdx.x * 8 + w;

    if (lane == 0) { candn[w] = 0; }
    __syncwarp();

    const uint4* p = (const uint4*)&g_S[(size_t)n * 512];
    uint4 q[4];
    float vals[4][8];
    float mn = 3.4e38f;
#pragma unroll
    for (int i = 0; i < 4; i++) {
        q[i] = p[lane + 32 * i];
        const unsigned* u = &q[i].x;
#pragma unroll
        for (int j = 0; j < 4; j++) {
            __half2 h = *(const __half2*)&u[j];
            float2 f = __half22float2(h);
            vals[i][2 * j] = f.x;
            vals[i][2 * j + 1] = f.y;
            mn = fminf(mn, fminf(f.x, f.y));
        }
    }
#pragma unroll
    for (int off = 16; off > 0; off >>= 1) mn = fminf(mn, __shfl_xor_sync(0xffffffffu, mn, off));

    float thr = mn + MARGIN;
#pragma unroll
    for (int i = 0; i < 4; i++)
#pragma unroll
        for (int j = 0; j < 8; j++) {
            if (vals[i][j] <= thr) {
                int k = (lane + 32 * i) * 8 + j;
                int pos = atomicAdd(&candn[w], 1);
                if (pos < NCAND) candk[w][pos] = k;
            }
        }
    __syncwarp();
    int nc = candn[w];

    float x[8];
    {
        const float4* xr = (const float4*)&g_flat[(size_t)n * DDIM + lane * 8];
        float4 a = xr[0], b = xr[1];
        x[0]=a.x; x[1]=a.y; x[2]=a.z; x[3]=a.w;
        x[4]=b.x; x[5]=b.y; x[6]=b.z; x[7]=b.w;
    }

    float bestd = 3.4e38f, second = 3.4e38f;
    int bestk = KCB;

    if (nc <= NCAND) {
        for (int ci = 0; ci < nc; ci++) {
            int kc = candk[w][ci];
            const float4* er = (const float4*)&emb[(size_t)kc * DDIM + lane * 8];
            float4 ea = er[0], eb = er[1];
            float d0=x[0]-ea.x, d1=x[1]-ea.y, d2=x[2]-ea.z, d3=x[3]-ea.w;
            float d4=x[4]-eb.x, d5=x[5]-eb.y, d6=x[6]-eb.z, d7=x[7]-eb.w;
            float pr = d0*d0+d1*d1+d2*d2+d3*d3+d4*d4+d5*d5+d6*d6+d7*d7;
#pragma unroll
            for (int off = 16; off > 0; off >>= 1) pr += __shfl_xor_sync(0xffffffffu, pr, off);
            if (pr < bestd) { second = bestd; bestd = pr; bestk = kc; }
            else if (pr < second) second = pr;
        }
        if (second <= bestd + TAU) {
            double bd = 1e300; int bk = KCB;
            for (int ci = 0; ci < nc; ci++) {
                int kc = candk[w][ci];
                const float4* er = (const float4*)&emb[(size_t)kc * DDIM + lane * 8];
                float4 ea = er[0], eb = er[1];
                double dp = 0.0;
#pragma unroll
                for (int qd = 0; qd < 4; qd++) {
                    double da = (double)x[qd]   - (double)(&ea.x)[qd];
                    double db = (double)x[qd+4] - (double)(&eb.x)[qd];
                    dp += da * da + db * db;
                }
#pragma unroll
                for (int off = 16; off > 0; off >>= 1) dp += __shfl_xor_sync(0xffffffffu, dp, off);
                if (dp < bd || (dp == bd && kc < bk)) { bd = dp; bk = kc; }
            }
            bestk = bk; bestd = (float)bd;
        }
    } else {
        for (int kc = 0; kc < KCB; kc++) {
            const float4* er = (const float4*)&emb[(size_t)kc * DDIM + lane * 8];
            float4 ea = er[0], eb = er[1];
            float d0=x[0]-ea.x, d1=x[1]-ea.y, d2=x[2]-ea.z, d3=x[3]-ea.w;
            float d4=x[4]-eb.x, d5=x[5]-eb.y, d6=x[6]-eb.z, d7=x[7]-eb.w;
            float pr = d0*d0+d1*d1+d2*d2+d3*d3+d4*d4+d5*d5+d6*d6+d7*d7;
#pragma unroll
            for (int off = 16; off > 0; off >>= 1) pr += __shfl_xor_sync(0xffffffffu, pr, off);
            if (pr < bestd) { second = bestd; bestd = pr; bestk = kc; }
            else if (pr < second) second = pr;
        }
        if (second <= bestd + TAU) {
            double bd = 1e300; int bk = KCB;
            for (int kc = 0; kc < KCB; kc++) {
                const float4* er = (const float4*)&emb[(size_t)kc * DDIM + lane * 8];
                float4 ea = er[0], eb = er[1];
                float d0=x[0]-ea.x, d1=x[1]-ea.y, d2=x[2]-ea.z, d3=x[3]-ea.w;
                float d4=x[4]-eb.x, d5=x[5]-eb.y, d6=x[6]-eb.z, d7=x[7]-eb.w;
                float pr = d0*d0+d1*d1+d2*d2+d3*d3+d4*d4+d5*d5+d6*d6+d7*d7;
#pragma unroll
                for (int off = 16; off > 0; off >>= 1) pr += __shfl_xor_sync(0xffffffffu, pr, off);
                if (pr <= bestd + TAU) {
                    double dp = 0.0;
#pragma unroll
                    for (int qd = 0; qd < 4; qd++) {
                        double da = (double)x[qd]   - (double)(&ea.x)[qd];
                        double db = (double)x[qd+4] - (double)(&eb.x)[qd];
                        dp += da * da + db * db;
                    }
#pragma unroll
                    for (int off = 16; off > 0; off >>= 1) dp += __shfl_xor_sync(0xffffffffu, dp, off);
                    if (dp < bd || (dp == bd && kc < bk)) { bd = dp; bk = kc; }
                }
            }
            bestk = bk; bestd = (float)bd;
        }
    }

    // one-hot encodings row
    float2* erow = (float2*)&enc[(size_t)n * KCB];
#pragma unroll
    for (int j = 0; j < 16; j++) {
        int idx2 = lane + 32 * j;
        float2 v;
        v.x = (2 * idx2     == bestk) ? 1.0f : 0.0f;
        v.y = (2 * idx2 + 1 == bestk) ? 1.0f : 0.0f;
        erow[idx2] = v;
    }

    if (lane == 0) {
        g_idx[n] = bestk;
        atomicAdd(&g_counts[bestk], 1);
        sloss[w] = (double)bestd;
    }
    __syncthreads();
    if (tid == 0) {
        double s = sloss[0] + sloss[1] + sloss[2] + sloss[3]
                 + sloss[4] + sloss[5] + sloss[6] + sloss[7];
        g_loss_part[blockIdx.x] = s;
    }
}

// ================= K5: quantized output (NCHW), smem-tiled =================
__global__ void k_out(float* __restrict__ out, const float* __restrict__ emb) {
    __shared__ float tile[32][257];
    __shared__ int kk[32];
    int tid = threadIdx.x;
    int b = blockIdx.y;
    int hw0 = blockIdx.x * 32;

    if (tid < 32) kk[tid] = g_idx[b * 1024 + hw0 + tid];
    __syncthreads();
#pragma unroll 4
    for (int tl = 0; tl < 32; tl++) {
        tile[tl][tid] = __ldg(&emb[((size_t)kk[tl] << 8) + tid]);
    }
    __syncthreads();
    int hw = tid & 31;
    int cb = tid >> 5;
#pragma unroll 4
    for (int cc = 0; cc < 32; cc++) {
        int ch = cb * 32 + cc;
        out[((size_t)(b * 256 + ch) << 10) + hw0 + hw] = tile[hw][ch];
    }
}

// ================= K6: finalize (warp scans + loss reduce) =================
__global__ void k_finalize(const float* __restrict__ ema_cs,
                           float* __restrict__ cluster_o,
                           float* __restrict__ loss_o,
                           float* __restrict__ ent_o) {
    __shared__ int    wsum[32];
    __shared__ float  red[32];
    __shared__ double dred[32];
    int t = threadIdx.x, w = t >> 5, l = t & 31;
    int cnt = g_counts[t];

    // loss reduction over 8192 partials
    double ls = 0.0;
#pragma unroll
    for (int i = 0; i < NREFBLK / 1024; i++) ls += g_loss_part[t + i * 1024];
#pragma unroll
    for (int off = 16; off > 0; off >>= 1) ls += __shfl_xor_sync(0xffffffffu, ls, off);
    if (l == 0) dred[w] = ls;

    int v = cnt;
#pragma unroll
    for (int off = 1; off < 32; off <<= 1) {
        int u = __shfl_up_sync(0xffffffffu, v, off);
        if (l >= off) v += u;
    }
    if (l == 31) wsum[w] = v;
    __syncthreads();
    if (w == 0) {
        int s = wsum[l];
#pragma unroll
        for (int off = 1; off < 32; off <<= 1) {
            int u = __shfl_up_sync(0xffffffffu, s, off);
            if (l >= off) s += u;
        }
        wsum[l] = s;
    }
    __syncthreads();
    int base = (w > 0) ? wsum[w - 1] : 0;
    g_start[t] = base + v - cnt;

    float cl = ema_cs[t] * DECAYF + ONE_M_DECAY * (float)cnt;
    float sv = cl;
#pragma unroll
    for (int off = 16; off > 0; off >>= 1) sv += __shfl_xor_sync(0xffffffffu, sv, off);
    if (l == 0) red[w] = sv;
    __syncthreads();
    if (w == 0) {
        float z = red[l];
#pragma unroll
        for (int off = 16; off > 0; off >>= 1) z += __shfl_xor_sync(0xffffffffu, z, off);
        red[l] = z;
    }
    __syncthreads();
    float nsum = red[0];
    __syncthreads();

    float cln = ((cl + EPSF) / (nsum + 1024.0f * EPSF)) * nsum;
    g_cluster[t] = cln;
    cluster_o[t] = cln;

    float p = (float)cnt * (1.0f / 65536.0f);
    float e = -p * logf(p + 1e-10f);
    float ev = e;
#pragma unroll
    for (int off = 16; off > 0; off >>= 1) ev += __shfl_xor_sync(0xffffffffu, ev, off);
    if (l == 0) red[w] = ev;
    __syncthreads();
    if (w == 0) {
        double lz = dred[l];
#pragma unroll
        for (int off = 16; off > 0; off >>= 1) lz += __shfl_xor_sync(0xffffffffu, lz, off);
        float z = red[l];
#pragma unroll
        for (int off = 16; off > 0; off >>= 1) z += __shfl_xor_sync(0xffffffffu, z, off);
        if (l == 0) {
            ent_o[0] = z;
            loss_o[0] = (float)(0.25 * lz / 16777216.0);
        }
    }
}

// ================= K7: bucket fill =================
__global__ void k_bucket() {
    int n = blockIdx.x * 256 + threadIdx.x;
    int k = g_idx[n];
    int p = atomicAdd(&g_pos[k], 1);
    g_bucket[g_start[k] + p] = n;
}

// ================= K8: dw + new_ema_w + new_embedding (warp-parallel) =================
__global__ void k_emaw(const float* __restrict__ ema_w,
                       float* __restrict__ emaw_o,
                       float* __restrict__ emb_o) {
    __shared__ float sacc[8][DDIM];
    int k = blockIdx.x;
    int tid = threadIdx.x, w = tid >> 5, lane = tid & 31;
    int cnt = g_counts[k], st = g_start[k];

    float acc[8];
#pragma unroll
    for (int j = 0; j < 8; j++) acc[j] = 0.f;

    for (int i = w; i < cnt; i += 8) {
        int n = g_bucket[st + i];
        const float4* r = (const float4*)&g_flat[(size_t)n * DDIM + lane * 8];
        float4 a = r[0], b = r[1];
        acc[0] += a.x; acc[1] += a.y; acc[2] += a.z; acc[3] += a.w;
        acc[4] += b.x; acc[5] += b.y; acc[6] += b.z; acc[7] += b.w;
    }
#pragma unroll
    for (int j = 0; j < 8; j++) sacc[w][lane * 8 + j] = acc[j];
    __syncthreads();

    int d = tid;
    float tot = 0.f;
#pragma unroll
    for (int w2 = 0; w2 < 8; w2++) tot += sacc[w2][d];
    float wv = ema_w[(size_t)k * DDIM + d] * DECAYF + ONE_M_DECAY * tot;
    emaw_o[(size_t)k * DDIM + d] = wv;
    emb_o[(size_t)k * DDIM + d] = wv / g_cluster[k];
}

// ================= launch =================
extern "C" void kernel_launch(void* const* d_in, const int* in_sizes, int n_in,
                              void* d_out, int out_size) {
    const float* inputs    = (const float*)d_in[0];
    const float* embedding = (const float*)d_in[1];
    const float* ema_cs    = (const float*)d_in[2];
    const float* ema_w     = (const float*)d_in[3];

    float* out    = (float*)d_out;
    float* loss_o = out + OFF_LOSS;
    float* ent_o  = out + OFF_ENT;
    float* enc    = out + OFF_ENC;
    float* clus_o = out + OFF_CLUSTER;
    float* emaw_o = out + OFF_EMAW;
    float* emb_o  = out + OFF_EMB;

    cudaFuncSetAttribute(k_gemm, cudaFuncAttributeMaxDynamicSharedMemorySize, SMEM_GEMM);

    k_embprep<<<KCB, 256>>>(embedding);
    k_transpose<<<dim3(32, 8, 64), dim3(32, 8)>>>(inputs);
    k_gemm<<<dim3(NTOK / 128, KCB / 128), 256, SMEM_GEMM>>>();
    k_refine<<<NREFBLK, 256>>>(enc, embedding);
    k_out<<<dim3(32, 64), 256>>>(out, embedding);
    k_finalize<<<1, 1024>>>(ema_cs, clus_o, loss_o, ent_o);
    k_bucket<<<NTOK / 256, 256>>>();
    k_emaw<<<KCB, 256>>>(ema_w, emaw_o, emb_o);
}